// round 11
// baseline (speedup 1.0000x reference)
#include <cuda_runtime.h>

// PSRoIPool. Probe: bin = roi * RN32(1/7) (reciprocal-multiply, as R9 showed
// moves toward golden), boundaries with SEPARATE mul/add rounding
// (XLA unfused elementwise lowering), not FMA.
//
// features: [4, 392, 128, 128] f32 ; rois: [R,5] f32 ; out: [R, 8, 7, 7] f32

#define RPS_FC 392
#define RPS_FH 128
#define RPS_FW 128
#define RPS_POOLED 7
#define RPS_ODIM 8
#define RPS_SCALE 0.0625f

__global__ void rps_main_v10(const float* __restrict__ feat,
                             const float* __restrict__ rois,
                             float* __restrict__ out, int total)
{
    const int i = blockIdx.x * blockDim.x + threadIdx.x;
    if (i >= total) return;

    int pw = i % RPS_POOLED;
    int t  = i / RPS_POOLED;
    int ph = t % RPS_POOLED;  t /= RPS_POOLED;
    int ct = t % RPS_ODIM;
    int r  = t / RPS_ODIM;

    const float* rp = rois + (size_t)r * 5;
    const int   b    = (int)rp[0];
    const float rs_w = rintf(rp[1]) * RPS_SCALE;            // exact (*2^-4)
    const float rs_h = rintf(rp[2]) * RPS_SCALE;
    const float re_w = (rintf(rp[3]) + 1.0f) * RPS_SCALE;   // exact
    const float re_h = (rintf(rp[4]) + 1.0f) * RPS_SCALE;

    const float RECIP7 = 0.142857149243354797363281250f;    // RN32(1/7)
    const float bin_h = __fmul_rn(fmaxf(__fadd_rn(re_h, -rs_h), 0.1f), RECIP7);
    const float bin_w = __fmul_rn(fmaxf(__fadd_rn(re_w, -rs_w), 0.1f), RECIP7);

    // SEPARATE rounding: RN(RN(p*bin) + rs)
    int hs = (int)floorf(__fadd_rn(__fmul_rn((float)ph,       bin_h), rs_h));
    int he = (int)ceilf (__fadd_rn(__fmul_rn((float)(ph + 1), bin_h), rs_h));
    int ws = (int)floorf(__fadd_rn(__fmul_rn((float)pw,       bin_w), rs_w));
    int we = (int)ceilf (__fadd_rn(__fmul_rn((float)(pw + 1), bin_w), rs_w));
    hs = min(max(hs, 0), RPS_FH);  he = min(max(he, 0), RPS_FH);
    ws = min(max(ws, 0), RPS_FW);  we = min(max(we, 0), RPS_FW);

    const int bh = he - hs;
    const int bw = we - ws;

    float val = 0.0f;
    if (bh > 0 && bw > 0) {
        const int c = (ct * RPS_POOLED + ph) * RPS_POOLED + pw;  // gh==ph, gw==pw
        const float* base = feat
            + (((size_t)b * RPS_FC + c) * RPS_FH + hs) * RPS_FW + ws;

        float s = 0.0f;
        for (int dh = 0; dh < bh; ++dh) {
            const float* row = base + dh * RPS_FW;
            #pragma unroll 4
            for (int dw = 0; dw < bw; ++dw)
                s += __ldg(row + dw);
        }
        val = s / (float)(bh * bw);
    }
    out[i] = val;
}

extern "C" void kernel_launch(void* const* d_in, const int* in_sizes, int n_in,
                              void* d_out, int out_size)
{
    const float* feat = (const float*)d_in[0];
    const float* rois = (const float*)d_in[1];
    float*       out  = (float*)d_out;

    const int total = out_size;   // R * 8 * 7 * 7

    rps_main_v10<<<(total + 255) / 256, 256>>>(feat, rois, out, total);
}

// round 12
// speedup vs baseline: 1.0571x; 1.0571x over previous
#include <cuda_runtime.h>

// PSRoIPool — CORRECTNESS-CRITICAL boundary math (verified R10, DO NOT CHANGE):
//   bin = fmax(re-rs, 0.1) * RN32(1/7)   (reciprocal multiply)
//   bound = RN(RN(p*bin) + rs)           (separate rounding, NO FMA)
// Perf: fully-unrolled 6x6 predicated load lattice (bh,bw <= 6 given
// wh <= 512px -> roi <= 32.1 -> bin <= 4.6), maximizing MLP; 128-thr blocks.
//
// features: [4, 392, 128, 128] f32 ; rois: [R,5] f32 ; out: [R, 8, 7, 7] f32

#define RPS_FC 392
#define RPS_FH 128
#define RPS_FW 128
#define RPS_POOLED 7
#define RPS_ODIM 8
#define RPS_SCALE 0.0625f
#define RPS_MAXB 6

__global__ void __launch_bounds__(128) rps_main_v11(
    const float* __restrict__ feat,
    const float* __restrict__ rois,
    float* __restrict__ out, int total)
{
    const int i = blockIdx.x * blockDim.x + threadIdx.x;
    if (i >= total) return;

    int pw = i % RPS_POOLED;
    int t  = i / RPS_POOLED;
    int ph = t % RPS_POOLED;  t /= RPS_POOLED;
    int ct = t % RPS_ODIM;
    int r  = t / RPS_ODIM;

    const float* rp = rois + (size_t)r * 5;
    const int   b    = (int)rp[0];
    const float rs_w = rintf(rp[1]) * RPS_SCALE;            // exact (*2^-4)
    const float rs_h = rintf(rp[2]) * RPS_SCALE;
    const float re_w = (rintf(rp[3]) + 1.0f) * RPS_SCALE;   // exact
    const float re_h = (rintf(rp[4]) + 1.0f) * RPS_SCALE;

    const float RECIP7 = 0.142857149243354797363281250f;    // RN32(1/7)
    const float bin_h = __fmul_rn(fmaxf(__fadd_rn(re_h, -rs_h), 0.1f), RECIP7);
    const float bin_w = __fmul_rn(fmaxf(__fadd_rn(re_w, -rs_w), 0.1f), RECIP7);

    // SEPARATE rounding: RN(RN(p*bin) + rs)  — verified against golden
    int hs = (int)floorf(__fadd_rn(__fmul_rn((float)ph,       bin_h), rs_h));
    int he = (int)ceilf (__fadd_rn(__fmul_rn((float)(ph + 1), bin_h), rs_h));
    int ws = (int)floorf(__fadd_rn(__fmul_rn((float)pw,       bin_w), rs_w));
    int we = (int)ceilf (__fadd_rn(__fmul_rn((float)(pw + 1), bin_w), rs_w));
    hs = min(max(hs, 0), RPS_FH);  he = min(max(he, 0), RPS_FH);
    ws = min(max(ws, 0), RPS_FW);  we = min(max(we, 0), RPS_FW);

    const int bh = he - hs;
    const int bw = we - ws;

    float val = 0.0f;
    if (bh > 0 && bw > 0) {
        const int c = (ct * RPS_POOLED + ph) * RPS_POOLED + pw;  // gh==ph, gw==pw
        const float* base = feat
            + (((size_t)b * RPS_FC + c) * RPS_FH + hs) * RPS_FW + ws;

        // Fully unrolled predicated lattice: all live loads issued up front.
        float acc[RPS_MAXB];
        #pragma unroll
        for (int dh = 0; dh < RPS_MAXB; ++dh) {
            float s = 0.0f;
            const float* row = base + dh * RPS_FW;
            #pragma unroll
            for (int dw = 0; dw < RPS_MAXB; ++dw)
                if (dh < bh && dw < bw) s += __ldg(row + dw);
            acc[dh] = s;
        }
        float ssum = ((acc[0] + acc[1]) + (acc[2] + acc[3])) + (acc[4] + acc[5]);
        val = ssum / (float)(bh * bw);
    }
    out[i] = val;
}

extern "C" void kernel_launch(void* const* d_in, const int* in_sizes, int n_in,
                              void* d_out, int out_size)
{
    const float* feat = (const float*)d_in[0];
    const float* rois = (const float*)d_in[1];
    float*       out  = (float*)d_out;

    const int total = out_size;   // R * 8 * 7 * 7

    rps_main_v11<<<(total + 127) / 128, 128>>>(feat, rois, out, total);
}

// round 13
// speedup vs baseline: 1.1866x; 1.1224x over previous
#include <cuda_runtime.h>

// PSRoIPool — CORRECTNESS-CRITICAL boundary math (verified R10, FROZEN):
//   bin = fmax(RN(re-rs), 0.1) * RN32(1/7)     (reciprocal multiply)
//   bound = RN(RN(p*bin) + rs)                 (separate rounding, NO FMA)
//
// Perf layout: warp = (r, ct, ph); lane = pw*4 + q. Each 4-lane quad sums one
// bin: per row, lane loads cols ws+q and ws+q+4 (pred < we) -> quad addresses
// contiguous within ONE channel row => ~1-2 sectors/quad/row (vs 32/warp-load
// in thread-per-output). 6 rows unrolled predicated for MLP; quad shfl reduce.
//
// features: [4, 392, 128, 128] f32 ; rois: [R,5] f32 ; out: [R, 8, 7, 7] f32

#define RPS_FC 392
#define RPS_FH 128
#define RPS_FW 128
#define RPS_POOLED 7
#define RPS_ODIM 8
#define RPS_SCALE 0.0625f

__global__ void __launch_bounds__(128) rps_main_v12(
    const float* __restrict__ feat,
    const float* __restrict__ rois,
    float* __restrict__ out, int n_warps)
{
    const int w    = (int)((blockIdx.x * blockDim.x + threadIdx.x) >> 5);
    const int lane = threadIdx.x & 31;
    if (w >= n_warps) return;

    // w -> (r, ct, ph)
    int ph = w % RPS_POOLED;
    int t  = w / RPS_POOLED;
    int ct = t % RPS_ODIM;
    int r  = t / RPS_ODIM;

    const int pw_raw = lane >> 2;                 // 0..7 (7 = idle quad)
    const int q      = lane & 3;
    const int active = pw_raw < RPS_POOLED;
    const int pw     = active ? pw_raw : (RPS_POOLED - 1);  // clamp for safety

    const float* rp = rois + (size_t)r * 5;
    const int   b    = (int)rp[0];
    const float rs_w = rintf(rp[1]) * RPS_SCALE;            // exact (*2^-4)
    const float rs_h = rintf(rp[2]) * RPS_SCALE;
    const float re_w = (rintf(rp[3]) + 1.0f) * RPS_SCALE;   // exact
    const float re_h = (rintf(rp[4]) + 1.0f) * RPS_SCALE;

    const float RECIP7 = 0.142857149243354797363281250f;    // RN32(1/7)
    const float bin_h = __fmul_rn(fmaxf(__fadd_rn(re_h, -rs_h), 0.1f), RECIP7);
    const float bin_w = __fmul_rn(fmaxf(__fadd_rn(re_w, -rs_w), 0.1f), RECIP7);

    // FROZEN separate rounding: RN(RN(p*bin) + rs)
    int hs = (int)floorf(__fadd_rn(__fmul_rn((float)ph,       bin_h), rs_h));
    int he = (int)ceilf (__fadd_rn(__fmul_rn((float)(ph + 1), bin_h), rs_h));
    int ws = (int)floorf(__fadd_rn(__fmul_rn((float)pw,       bin_w), rs_w));
    int we = (int)ceilf (__fadd_rn(__fmul_rn((float)(pw + 1), bin_w), rs_w));
    hs = min(max(hs, 0), RPS_FH);  he = min(max(he, 0), RPS_FH);
    ws = min(max(ws, 0), RPS_FW);  we = min(max(we, 0), RPS_FW);

    const int bh = he - hs;
    const int bw = we - ws;

    const int c = (ct * RPS_POOLED + ph) * RPS_POOLED + pw;   // gh==ph, gw==pw
    const float* base = feat
        + (((size_t)b * RPS_FC + c) * RPS_FH + hs) * RPS_FW;  // row hs, col 0

    // Lane's two candidate columns inside the bin.
    const int c0 = ws + q;
    const int c1 = ws + q + 4;
    const bool p0 = (q     < bw);   // c0 < we
    const bool p1 = (q + 4 < bw);   // c1 < we

    float s = 0.0f;
    #pragma unroll
    for (int dh = 0; dh < 6; ++dh) {
        const bool pr = (dh < bh);
        const float* row = base + dh * RPS_FW;
        if (pr && p0) s += __ldg(row + c0);
        if (pr && p1) s += __ldg(row + c1);
    }

    // Quad reduction (lanes pw*4 .. pw*4+3).
    s += __shfl_xor_sync(0xffffffffu, s, 1);
    s += __shfl_xor_sync(0xffffffffu, s, 2);

    if (q == 0 && active) {
        float val = 0.0f;
        if (bh > 0 && bw > 0) val = s / (float)(bh * bw);
        out[((size_t)w * RPS_POOLED) + pw_raw] = val;
    }
}

extern "C" void kernel_launch(void* const* d_in, const int* in_sizes, int n_in,
                              void* d_out, int out_size)
{
    const float* feat = (const float*)d_in[0];
    const float* rois = (const float*)d_in[1];
    float*       out  = (float*)d_out;

    const int R = in_sizes[1] / 5;
    const int n_warps = R * RPS_ODIM * RPS_POOLED;        // one warp per (r,ct,ph)
    const int threads = 128;                              // 4 warps/block
    const int blocks  = (n_warps * 32 + threads - 1) / threads;

    rps_main_v12<<<blocks, threads>>>(feat, rois, out, n_warps);
}